// round 5
// baseline (speedup 1.0000x reference)
#include <cuda_runtime.h>
#include <cuda_bf16.h>

#define B     64
#define S     512
#define TF    1024
#define TD    128
#define V     1000
#define KW    31
#define PAD   15
#define TT    32   // t-tile in scores kernel

// ---------------- scratch (device globals; no allocation allowed) ----------------
__device__ float g_keysT[(size_t)B * S * TF];   // keys transposed: [b][s][t]
__device__ float g_h[B * S];
__device__ float g_ctx[B * S];
__device__ float g_q[B * S];                    // q + bq + conv_b folded
__device__ float g_gi[B * 3 * S];
__device__ float g_gh[B * 3 * S];
__device__ float g_scores[B * TF];
__device__ float g_w[B * TF];
__device__ float g_cwT[KW * S];                 // conv filters transposed: [k][s]

// ---------------- helpers ----------------
__device__ __forceinline__ float fast_tanh(float x) {
    float e = __expf(2.0f * x);
    return 1.0f - 2.0f / (e + 1.0f);
}
__device__ __forceinline__ float fast_sigmoid(float x) {
    return 1.0f / (1.0f + __expf(-x));
}

// ---------------- init: zero recurrent state ----------------
__global__ void init_kernel() {
    int idx = blockIdx.x * 256 + threadIdx.x;
    if (idx < B * S) { g_h[idx] = 0.0f; g_ctx[idx] = 0.0f; }
    if (idx < B * TF) g_w[idx] = 0.0f;
}

// ---------------- transpose conv filters: [s][k] -> [k][s] ----------------
__global__ void cw_transpose_kernel(const float* __restrict__ conv_w) {
    int idx = blockIdx.x * 256 + threadIdx.x;
    if (idx < S * KW) {
        int s = idx / KW, k = idx % KW;
        g_cwT[k * S + s] = conv_w[idx];
    }
}

// ---------------- keys precompute: keysT[b][n][t] = sum_k F[b,t,k]*Wk[n,k] + bk[n] ----------------
// GEMM: M = B*TF (=65536) rows of features, N = S, K = S. 64x64 tile, 256 thr, 4x4/thread.
__global__ __launch_bounds__(256) void keys_gemm_kernel(
    const float* __restrict__ features, const float* __restrict__ Wk,
    const float* __restrict__ bk)
{
    __shared__ float As[16][68];
    __shared__ float Bs[16][68];
    int tid = threadIdx.x;
    int m0 = blockIdx.x * 64, n0 = blockIdx.y * 64;
    int lr = tid & 63, lk = tid >> 6;     // load row, k-segment (0..3)
    int tx = tid & 15, ty = tid >> 4;     // compute coords
    float c[4][4] = {};

    for (int k0 = 0; k0 < S; k0 += 16) {
        float4 a = *(const float4*)(features + (size_t)(m0 + lr) * S + k0 + lk * 4);
        float4 bv = *(const float4*)(Wk + (size_t)(n0 + lr) * S + k0 + lk * 4);
        __syncthreads();
        As[lk * 4 + 0][lr] = a.x;  As[lk * 4 + 1][lr] = a.y;
        As[lk * 4 + 2][lr] = a.z;  As[lk * 4 + 3][lr] = a.w;
        Bs[lk * 4 + 0][lr] = bv.x; Bs[lk * 4 + 1][lr] = bv.y;
        Bs[lk * 4 + 2][lr] = bv.z; Bs[lk * 4 + 3][lr] = bv.w;
        __syncthreads();
#pragma unroll
        for (int k = 0; k < 16; k++) {
            float4 av = *(const float4*)&As[k][ty * 4];
            float4 bw = *(const float4*)&Bs[k][tx * 4];
            c[0][0] = fmaf(av.x, bw.x, c[0][0]); c[0][1] = fmaf(av.x, bw.y, c[0][1]);
            c[0][2] = fmaf(av.x, bw.z, c[0][2]); c[0][3] = fmaf(av.x, bw.w, c[0][3]);
            c[1][0] = fmaf(av.y, bw.x, c[1][0]); c[1][1] = fmaf(av.y, bw.y, c[1][1]);
            c[1][2] = fmaf(av.y, bw.z, c[1][2]); c[1][3] = fmaf(av.y, bw.w, c[1][3]);
            c[2][0] = fmaf(av.z, bw.x, c[2][0]); c[2][1] = fmaf(av.z, bw.y, c[2][1]);
            c[2][2] = fmaf(av.z, bw.z, c[2][2]); c[2][3] = fmaf(av.z, bw.w, c[2][3]);
            c[3][0] = fmaf(av.w, bw.x, c[3][0]); c[3][1] = fmaf(av.w, bw.y, c[3][1]);
            c[3][2] = fmaf(av.w, bw.z, c[3][2]); c[3][3] = fmaf(av.w, bw.w, c[3][3]);
        }
    }
    int bb = m0 >> 10;                  // whole tile lies within one b (64 | 1024)
    int tbase = (m0 & 1023) + ty * 4;
#pragma unroll
    for (int j = 0; j < 4; j++) {
        int n = n0 + tx * 4 + j;
        float bias = bk[n];
        float* dst = g_keysT + ((size_t)bb * S + n) * TF + tbase;
#pragma unroll
        for (int i = 0; i < 4; i++) dst[i] = c[i][j] + bias;
    }
}

// ---------------- skinny step GEMM (M=64), NT layout: C = A @ B^T + bias ----------------
// mode 0: gi  = x @ W_ih^T + b_ih     (x = [emb_t | ctx], K=1024, N=1536) -> g_gi
// mode 1: gh  = h @ W_hh^T + b_hh     (K=512,  N=1536)                    -> g_gh
// mode 2: q'  = h @ Wq^T + bq + conv_b (K=512, N=512)                     -> g_q
// mode 3: out = [h|ctx] @ Wo^T + bo   (K=1024, N=1000)                    -> outs[:, t, :]
//
// mode_base = 0: prologue, modes {0,1} via blockIdx.y, gates at t_gates
// mode_base = 2: q only
// mode_base = 3: combined: y==0 -> logits at t_logits; y==1 -> mode 0 at t_gates;
//                y==2 -> mode 1. (logits_t and gates_{t+1} both depend only on h_t, ctx_t)
__global__ __launch_bounds__(256) void step_gemm_kernel(
    int mode_base,
    const int* __restrict__ input_ids, const float* __restrict__ emb,
    const float* __restrict__ W_ih, const float* __restrict__ W_hh,
    const float* __restrict__ b_ih, const float* __restrict__ b_hh,
    const float* __restrict__ Wq, const float* __restrict__ bq,
    const float* __restrict__ conv_b,
    const float* __restrict__ Wo, const float* __restrict__ bo,
    float* __restrict__ outs, int t_logits, int t_gates)
{
    int mode;
    if (mode_base == 0)      mode = blockIdx.y;                       // 0 or 1
    else if (mode_base == 2) mode = 2;
    else                     mode = (blockIdx.y == 0) ? 3 : (int)blockIdx.y - 1;

    int K, N;
    const float* Bm;
    const float* bias;
    if (mode == 0)      { K = 1024; N = 3 * S; Bm = W_ih; bias = b_ih; }
    else if (mode == 1) { K = 512;  N = 3 * S; Bm = W_hh; bias = b_hh; }
    else if (mode == 2) { K = 512;  N = S;     Bm = Wq;   bias = bq;   }
    else                { K = 1024; N = V;     Bm = Wo;   bias = bo;   }

    int n0 = blockIdx.x * 32;
    if (n0 >= N) return;     // combined launch uses max grid.x across modes

    __shared__ float As[32][68];
    __shared__ float Bs[32][34];
    __shared__ int s_idx[64];

    int tid = threadIdx.x;
    if (mode == 0 && tid < 64) s_idx[tid] = input_ids[tid * TD + t_gates];
    __syncthreads();

    int tx = tid & 15, ty = tid >> 4;      // n = n0 + tx*2 + {0,1}, m = ty*4 + {0..3}
    int am = tid & 63, akseg = tid >> 6;   // A loads: row am, k chunk of 8
    int bn = tid & 31, bkseg = tid >> 5;   // B loads: row bn, k chunk of 4
    float c[4][2] = {};

    for (int k0 = 0; k0 < K; k0 += 32) {
        int kbase = k0 + akseg * 8;
        const float* ap;
        if (mode == 0) {
            if (kbase < 512) ap = emb + (size_t)s_idx[am] * S + kbase;
            else             ap = g_ctx + am * S + (kbase - 512);
        } else if (mode == 3) {
            if (kbase < 512) ap = g_h + am * S + kbase;
            else             ap = g_ctx + am * S + (kbase - 512);
        } else {
            ap = g_h + am * S + kbase;
        }
        float4 a0 = *(const float4*)ap;
        float4 a1 = *(const float4*)(ap + 4);

        int gn = n0 + bn;
        float4 bv = make_float4(0.f, 0.f, 0.f, 0.f);
        if (gn < N) bv = *(const float4*)(Bm + (size_t)gn * K + k0 + bkseg * 4);

        __syncthreads();
        As[akseg * 8 + 0][am] = a0.x; As[akseg * 8 + 1][am] = a0.y;
        As[akseg * 8 + 2][am] = a0.z; As[akseg * 8 + 3][am] = a0.w;
        As[akseg * 8 + 4][am] = a1.x; As[akseg * 8 + 5][am] = a1.y;
        As[akseg * 8 + 6][am] = a1.z; As[akseg * 8 + 7][am] = a1.w;
        Bs[bkseg * 4 + 0][bn] = bv.x; Bs[bkseg * 4 + 1][bn] = bv.y;
        Bs[bkseg * 4 + 2][bn] = bv.z; Bs[bkseg * 4 + 3][bn] = bv.w;
        __syncthreads();
#pragma unroll
        for (int k = 0; k < 32; k++) {
            float4 a = *(const float4*)&As[k][ty * 4];
            float2 b = *(const float2*)&Bs[k][tx * 2];
            c[0][0] = fmaf(a.x, b.x, c[0][0]); c[0][1] = fmaf(a.x, b.y, c[0][1]);
            c[1][0] = fmaf(a.y, b.x, c[1][0]); c[1][1] = fmaf(a.y, b.y, c[1][1]);
            c[2][0] = fmaf(a.z, b.x, c[2][0]); c[2][1] = fmaf(a.z, b.y, c[2][1]);
            c[3][0] = fmaf(a.w, b.x, c[3][0]); c[3][1] = fmaf(a.w, b.y, c[3][1]);
        }
    }

#pragma unroll
    for (int i = 0; i < 4; i++) {
#pragma unroll
        for (int j = 0; j < 2; j++) {
            int gn = n0 + tx * 2 + j;
            int m = ty * 4 + i;
            float bv = (gn < N) ? bias[gn] : 0.0f;
            float val = c[i][j] + bv;
            if (mode == 0)      g_gi[m * (3 * S) + gn] = val;
            else if (mode == 1) g_gh[m * (3 * S) + gn] = val;
            else if (mode == 2) g_q[m * S + gn] = val + conv_b[gn];
            else if (gn < N)
                outs[((size_t)m * TD + t_logits) * (size_t)V + gn] = val;
        }
    }
}

// ---------------- GRU gate combine ----------------
__global__ __launch_bounds__(256) void h_update_kernel() {
    int idx = blockIdx.x * 256 + threadIdx.x;   // B*S = 32768
    int b = idx >> 9, j = idx & 511;
    int base = b * (3 * S);
    float gir = g_gi[base + j], giz = g_gi[base + 512 + j], gin = g_gi[base + 1024 + j];
    float ghr = g_gh[base + j], ghz = g_gh[base + 512 + j], ghn = g_gh[base + 1024 + j];
    float r = fast_sigmoid(gir + ghr);
    float z = fast_sigmoid(giz + ghz);
    float n = fast_tanh(gin + r * ghn);
    float h = g_h[idx];
    g_h[idx] = (1.0f - z) * n + z * h;
}

// ---------------- attention scores: fused location-conv + tanh + v-dot ----------------
// scores[b,t] = sum_s v[s]*tanh(q'[b,s] + keysT[b,s,t] + sum_k cw[s,k]*w_prev[b,t+k-PAD])
// block = (t-tile of 32, b), 512 threads (one per s). Thread keeps 31 taps + 32 accs in regs.
__global__ __launch_bounds__(512) void scores_kernel(const float* __restrict__ v_vec) {
    const int b = blockIdx.y;
    const int t0 = blockIdx.x * TT;
    const int s = threadIdx.x;

    __shared__ float s_win[TT + KW - 1];   // 62
    __shared__ float s_red[16][TT + 1];

    if (s < TT + KW - 1) {
        int t = t0 + s - PAD;
        s_win[s] = (t >= 0 && t < TF) ? g_w[b * TF + t] : 0.0f;
    }
    __syncthreads();

    float cw[KW];
#pragma unroll
    for (int k = 0; k < KW; k++) cw[k] = g_cwT[k * S + s];
    float qv = g_q[b * S + s];
    float vs = v_vec[s];

    float acc[TT];
    const float* kp = g_keysT + ((size_t)b * S + s) * TF + t0;
#pragma unroll
    for (int j = 0; j < TT; j += 4) {
        float4 kv = *(const float4*)(kp + j);
        acc[j + 0] = qv + kv.x; acc[j + 1] = qv + kv.y;
        acc[j + 2] = qv + kv.z; acc[j + 3] = qv + kv.w;
    }
    // diagonal ordering: one broadcast LDS per window element (62 total)
#pragma unroll
    for (int i = 0; i < TT + KW - 1; i++) {
        float wv = s_win[i];
#pragma unroll
        for (int j = 0; j < TT; j++) {
            int k = i - j;
            if (k >= 0 && k < KW) acc[j] = fmaf(cw[k], wv, acc[j]);
        }
    }
    // tanh, weight by v[s], reduce over s (warp butterfly + smem combine)
#pragma unroll
    for (int j = 0; j < TT; j++) {
        float e = __expf(2.0f * acc[j]);
        float cval = vs * (1.0f - 2.0f / (e + 1.0f));
#pragma unroll
        for (int off = 16; off > 0; off >>= 1)
            cval += __shfl_xor_sync(0xffffffffu, cval, off);
        acc[j] = cval;
    }
    int warp = s >> 5, lane = s & 31;
    if (lane == 0) {
#pragma unroll
        for (int j = 0; j < TT; j++) s_red[warp][j] = acc[j];
    }
    __syncthreads();
    if (s < TT) {
        float sum = 0.0f;
#pragma unroll
        for (int w = 0; w < 16; w++) sum += s_red[w][s];
        g_scores[b * TF + t0 + s] = sum;
    }
}

// ---------------- softmax over Tf; writes g_w and ws output ----------------
__global__ __launch_bounds__(256) void softmax_kernel(float* __restrict__ ws, int t_step) {
    int b = blockIdx.x, tid = threadIdx.x;
    __shared__ float s_r[8];
    float vals[4];
    float m = -1e30f;
#pragma unroll
    for (int i = 0; i < 4; i++) {
        vals[i] = g_scores[b * TF + tid + i * 256];
        m = fmaxf(m, vals[i]);
    }
#pragma unroll
    for (int off = 16; off > 0; off >>= 1)
        m = fmaxf(m, __shfl_xor_sync(0xffffffffu, m, off));
    if ((tid & 31) == 0) s_r[tid >> 5] = m;
    __syncthreads();
    m = s_r[0];
#pragma unroll
    for (int w = 1; w < 8; w++) m = fmaxf(m, s_r[w]);
    __syncthreads();

    float sum = 0.0f;
#pragma unroll
    for (int i = 0; i < 4; i++) { vals[i] = __expf(vals[i] - m); sum += vals[i]; }
#pragma unroll
    for (int off = 16; off > 0; off >>= 1)
        sum += __shfl_xor_sync(0xffffffffu, sum, off);
    if ((tid & 31) == 0) s_r[tid >> 5] = sum;
    __syncthreads();
    float total = 0.0f;
#pragma unroll
    for (int w = 0; w < 8; w++) total += s_r[w];
    float inv = 1.0f / total;
#pragma unroll
    for (int i = 0; i < 4; i++) {
        int t = tid + i * 256;
        float wv = vals[i] * inv;
        g_w[b * TF + t] = wv;
        ws[((size_t)b * TD + t_step) * (size_t)TF + t] = wv;
    }
}

// ---------------- context: ctx[b,d] = sum_t w[b,t] * features[b,t,d] ----------------
__global__ __launch_bounds__(128) void ctx_kernel(const float* __restrict__ features) {
    int b = blockIdx.y;
    int d = blockIdx.x * 128 + threadIdx.x;
    __shared__ float s_w[TF];
    for (int i = threadIdx.x; i < TF; i += 128) s_w[i] = g_w[b * TF + i];
    __syncthreads();
    const float* f = features + (size_t)b * TF * S + d;
    float a0 = 0.f, a1 = 0.f, a2 = 0.f, a3 = 0.f;
#pragma unroll 2
    for (int t = 0; t < TF; t += 4) {
        a0 = fmaf(s_w[t + 0], f[(size_t)(t + 0) * S], a0);
        a1 = fmaf(s_w[t + 1], f[(size_t)(t + 1) * S], a1);
        a2 = fmaf(s_w[t + 2], f[(size_t)(t + 2) * S], a2);
        a3 = fmaf(s_w[t + 3], f[(size_t)(t + 3) * S], a3);
    }
    g_ctx[b * S + d] = (a0 + a1) + (a2 + a3);
}

// ---------------- launch ----------------
extern "C" void kernel_launch(void* const* d_in, const int* in_sizes, int n_in,
                              void* d_out, int out_size) {
    const int*   input    = (const int*)d_in[0];
    const float* features = (const float*)d_in[1];
    const float* emb      = (const float*)d_in[2];
    const float* W_ih     = (const float*)d_in[3];
    const float* W_hh     = (const float*)d_in[4];
    const float* b_ih     = (const float*)d_in[5];
    const float* b_hh     = (const float*)d_in[6];
    const float* Wq       = (const float*)d_in[7];
    const float* bq       = (const float*)d_in[8];
    const float* Wk       = (const float*)d_in[9];
    const float* bk       = (const float*)d_in[10];
    const float* conv_w   = (const float*)d_in[11];
    const float* conv_b   = (const float*)d_in[12];
    const float* v_vec    = (const float*)d_in[13];
    const float* Wo       = (const float*)d_in[14];
    const float* bo       = (const float*)d_in[15];

    float* outs = (float*)d_out;                        // [B, TD, V]
    float* ws   = outs + (size_t)B * TD * V;            // [B, TD, TF]

    init_kernel<<<(B * TF + 255) / 256, 256>>>();
    cw_transpose_kernel<<<(S * KW + 255) / 256, 256>>>(conv_w);
    keys_gemm_kernel<<<dim3((B * TF) / 64, S / 64), 256>>>(features, Wk, bk);

    // prologue: gi/gh for t=0 (h0 = ctx0 = 0)
    step_gemm_kernel<<<dim3((3 * S) / 32, 2), 256>>>(
        0, input, emb, W_ih, W_hh, b_ih, b_hh, Wq, bq, conv_b, Wo, bo, outs, 0, 0);

    for (int t = 0; t < TD; ++t) {
        h_update_kernel<<<(B * S) / 256, 256>>>();
        // q = h @ Wq^T + bq + conv_b (mode 2)
        step_gemm_kernel<<<dim3(S / 32, 1), 256>>>(
            2, input, emb, W_ih, W_hh, b_ih, b_hh, Wq, bq, conv_b, Wo, bo, outs, t, t);
        scores_kernel<<<dim3(TF / TT, B), 512>>>(v_vec);
        softmax_kernel<<<B, 256>>>(ws, t);
        ctx_kernel<<<dim3(S / 128, B), 128>>>(features);
        // combined: logits_t (+ gi/gh for t+1 when t < TD-1)
        int gy = (t < TD - 1) ? 3 : 1;
        step_gemm_kernel<<<dim3((3 * S) / 32, gy), 256>>>(
            3, input, emb, W_ih, W_hh, b_ih, b_hh, Wq, bq, conv_b, Wo, bo, outs, t, t + 1);
    }
}

// round 8
// speedup vs baseline: 1.2005x; 1.2005x over previous
#include <cuda_runtime.h>
#include <cuda_bf16.h>

#define B     64
#define S     512
#define TF    1024
#define TD    128
#define V     1000
#define KW    31
#define PAD   15
#define TT    16   // t-tile in scores kernel

typedef unsigned long long u64;

// ---------------- scratch (device globals; no allocation allowed) ----------------
__device__ float g_keysT[(size_t)B * S * TF];   // keys transposed: [b][s][t]
__device__ float g_h[B * S];
__device__ float g_ctx[B * S];
__device__ float g_w[B * TF];
__device__ float g_scores[B * TF];
__device__ float g_cwT[KW * S];                 // conv filters transposed: [k][s]
__device__ float g_qbias[S];                    // bq + conv_b
// split-K partial buffers (written whole each step; no zeroing needed)
__device__ float g_giP[4][B * 3 * S];
__device__ float g_ghP[2][B * 3 * S];
__device__ float g_qP[4][B * S];
__device__ float g_loP[4][B * V];

// ---------------- f32x2 helpers ----------------
__device__ __forceinline__ u64 pack2(float lo, float hi) {
    u64 r; asm("mov.b64 %0, {%1,%2};" : "=l"(r) : "f"(lo), "f"(hi)); return r;
}
__device__ __forceinline__ void unpack2(u64 v, float& lo, float& hi) {
    asm("mov.b64 {%0,%1}, %2;" : "=f"(lo), "=f"(hi) : "l"(v));
}
__device__ __forceinline__ u64 add2(u64 a, u64 b) {
    u64 r; asm("add.rn.f32x2 %0, %1, %2;" : "=l"(r) : "l"(a), "l"(b)); return r;
}
__device__ __forceinline__ u64 fma2(u64 a, u64 b, u64 c) {
    u64 r; asm("fma.rn.f32x2 %0, %1, %2, %3;" : "=l"(r) : "l"(a), "l"(b), "l"(c)); return r;
}

__device__ __forceinline__ float fast_tanh(float x) {
    float e = __expf(2.0f * x);
    return 1.0f - 2.0f / (e + 1.0f);
}
__device__ __forceinline__ float fast_sigmoid(float x) {
    return 1.0f / (1.0f + __expf(-x));
}

// ---------------- init: zero recurrent state ----------------
__global__ void init_kernel() {
    int idx = blockIdx.x * 256 + threadIdx.x;
    if (idx < B * S) { g_h[idx] = 0.0f; g_ctx[idx] = 0.0f; }
    if (idx < B * TF) g_w[idx] = 0.0f;
}

// ---------------- transpose conv filters + qbias ----------------
__global__ void cw_transpose_kernel(const float* __restrict__ conv_w,
                                    const float* __restrict__ bq,
                                    const float* __restrict__ conv_b) {
    int idx = blockIdx.x * 256 + threadIdx.x;
    if (idx < S * KW) {
        int s = idx / KW, k = idx % KW;
        g_cwT[k * S + s] = conv_w[idx];
    }
    if (idx < S) g_qbias[idx] = bq[idx] + conv_b[idx];
}

// ---------------- keys precompute: keysT[b][n][t] = sum_k F[b,t,k]*Wk[n,k] + bk[n] ----------------
__global__ __launch_bounds__(256) void keys_gemm_kernel(
    const float* __restrict__ features, const float* __restrict__ Wk,
    const float* __restrict__ bk)
{
    __shared__ float As[16][68];
    __shared__ float Bs[16][68];
    int tid = threadIdx.x;
    int m0 = blockIdx.x * 64, n0 = blockIdx.y * 64;
    int lr = tid & 63, lk = tid >> 6;
    int tx = tid & 15, ty = tid >> 4;
    float c[4][4] = {};

    for (int k0 = 0; k0 < S; k0 += 16) {
        float4 a = *(const float4*)(features + (size_t)(m0 + lr) * S + k0 + lk * 4);
        float4 bv = *(const float4*)(Wk + (size_t)(n0 + lr) * S + k0 + lk * 4);
        __syncthreads();
        As[lk * 4 + 0][lr] = a.x;  As[lk * 4 + 1][lr] = a.y;
        As[lk * 4 + 2][lr] = a.z;  As[lk * 4 + 3][lr] = a.w;
        Bs[lk * 4 + 0][lr] = bv.x; Bs[lk * 4 + 1][lr] = bv.y;
        Bs[lk * 4 + 2][lr] = bv.z; Bs[lk * 4 + 3][lr] = bv.w;
        __syncthreads();
#pragma unroll
        for (int k = 0; k < 16; k++) {
            float4 av = *(const float4*)&As[k][ty * 4];
            float4 bw = *(const float4*)&Bs[k][tx * 4];
            c[0][0] = fmaf(av.x, bw.x, c[0][0]); c[0][1] = fmaf(av.x, bw.y, c[0][1]);
            c[0][2] = fmaf(av.x, bw.z, c[0][2]); c[0][3] = fmaf(av.x, bw.w, c[0][3]);
            c[1][0] = fmaf(av.y, bw.x, c[1][0]); c[1][1] = fmaf(av.y, bw.y, c[1][1]);
            c[1][2] = fmaf(av.y, bw.z, c[1][2]); c[1][3] = fmaf(av.y, bw.w, c[1][3]);
            c[2][0] = fmaf(av.z, bw.x, c[2][0]); c[2][1] = fmaf(av.z, bw.y, c[2][1]);
            c[2][2] = fmaf(av.z, bw.z, c[2][2]); c[2][3] = fmaf(av.z, bw.w, c[2][3]);
            c[3][0] = fmaf(av.w, bw.x, c[3][0]); c[3][1] = fmaf(av.w, bw.y, c[3][1]);
            c[3][2] = fmaf(av.w, bw.z, c[3][2]); c[3][3] = fmaf(av.w, bw.w, c[3][3]);
        }
    }
    int bb = m0 >> 10;
    int tbase = (m0 & 1023) + ty * 4;
#pragma unroll
    for (int j = 0; j < 4; j++) {
        int n = n0 + tx * 4 + j;
        float bias = bk[n];
        float* dst = g_keysT + ((size_t)bb * S + n) * TF + tbase;
#pragma unroll
        for (int i = 0; i < 4; i++) dst[i] = c[i][j] + bias;
    }
}

// ---------------- split-K skinny GEMM: 64x64 tile, 4x4/thread, partials, NO bias ----------------
// mode 0: gi partials  = x @ W_ih^T   (x=[emb|ctx], Ktot=1024, Ksl=256, 4 slices, N=1536)
// mode 1: gh partials  = h @ W_hh^T   (Ktot=512,  Ksl=256, 2 slices, N=1536)
// mode 2: q  partials  = h @ Wq^T     (Ktot=512,  Ksl=128, 4 slices, N=512)
// mode 3: logits part. = [h|ctx]@Wo^T (Ktot=1024, Ksl=256, 4 slices, N=1000)
// mb=0: y<4 -> mode0 slice y; y<6 -> mode1 slice y-4; y>=6 -> mode3 slice y-6
// mb=2: mode2 slice y.   mb=3: mode3 slice y.
__global__ __launch_bounds__(256) void gemm64_kernel(
    int mb,
    const int* __restrict__ input_ids, const float* __restrict__ emb,
    const float* __restrict__ W_ih, const float* __restrict__ W_hh,
    const float* __restrict__ Wq, const float* __restrict__ Wo,
    int t_gates)
{
    int by = blockIdx.y;
    int mode, sl;
    if (mb == 2)      { mode = 2; sl = by; }
    else if (mb == 3) { mode = 3; sl = by; }
    else {
        if (by < 4)      { mode = 0; sl = by; }
        else if (by < 6) { mode = 1; sl = by - 4; }
        else             { mode = 3; sl = by - 6; }
    }

    int N, Ktot, Ksl, strideN;
    const float* Bmat;
    float* dst;
    if (mode == 0)      { N = 3*S; Ktot = 1024; Ksl = 256; Bmat = W_ih; dst = g_giP[sl]; strideN = 3*S; }
    else if (mode == 1) { N = 3*S; Ktot = 512;  Ksl = 256; Bmat = W_hh; dst = g_ghP[sl]; strideN = 3*S; }
    else if (mode == 2) { N = S;   Ktot = 512;  Ksl = 128; Bmat = Wq;   dst = g_qP[sl];  strideN = S; }
    else                { N = V;   Ktot = 1024; Ksl = 256; Bmat = Wo;   dst = g_loP[sl]; strideN = V; }

    int n0 = blockIdx.x * 64;
    if (n0 >= N) return;

    __shared__ float As[16][68];
    __shared__ float Bs[16][68];
    __shared__ int s_idx[64];

    int tid = threadIdx.x;
    if (mode == 0 && tid < 64) s_idx[tid] = input_ids[tid * TD + t_gates];
    __syncthreads();

    int lr = tid & 63, lk = tid >> 6;     // load row / k-seg*4
    int tx = tid & 15, ty = tid >> 4;     // n-tile col / m-tile row
    float c[4][4] = {};

    for (int kc = 0; kc < Ksl; kc += 16) {
        int kb = sl * Ksl + kc + lk * 4;
        const float* ap;
        if (mode == 0) {
            if (kb < 512) ap = emb + (size_t)s_idx[lr] * S + kb;
            else          ap = g_ctx + lr * S + (kb - 512);
        } else if (mode == 3) {
            if (kb < 512) ap = g_h + lr * S + kb;
            else          ap = g_ctx + lr * S + (kb - 512);
        } else {
            ap = g_h + lr * S + kb;
        }
        float4 a = *(const float4*)ap;

        int gn = n0 + lr;
        float4 bv = make_float4(0.f, 0.f, 0.f, 0.f);
        if (gn < N) bv = *(const float4*)(Bmat + (size_t)gn * Ktot + kb);

        __syncthreads();
        As[lk * 4 + 0][lr] = a.x;  As[lk * 4 + 1][lr] = a.y;
        As[lk * 4 + 2][lr] = a.z;  As[lk * 4 + 3][lr] = a.w;
        Bs[lk * 4 + 0][lr] = bv.x; Bs[lk * 4 + 1][lr] = bv.y;
        Bs[lk * 4 + 2][lr] = bv.z; Bs[lk * 4 + 3][lr] = bv.w;
        __syncthreads();
#pragma unroll
        for (int k = 0; k < 16; k++) {
            float4 av = *(const float4*)&As[k][ty * 4];
            float4 bw = *(const float4*)&Bs[k][tx * 4];
            c[0][0] = fmaf(av.x, bw.x, c[0][0]); c[0][1] = fmaf(av.x, bw.y, c[0][1]);
            c[0][2] = fmaf(av.x, bw.z, c[0][2]); c[0][3] = fmaf(av.x, bw.w, c[0][3]);
            c[1][0] = fmaf(av.y, bw.x, c[1][0]); c[1][1] = fmaf(av.y, bw.y, c[1][1]);
            c[1][2] = fmaf(av.y, bw.z, c[1][2]); c[1][3] = fmaf(av.y, bw.w, c[1][3]);
            c[2][0] = fmaf(av.z, bw.x, c[2][0]); c[2][1] = fmaf(av.z, bw.y, c[2][1]);
            c[2][2] = fmaf(av.z, bw.z, c[2][2]); c[2][3] = fmaf(av.z, bw.w, c[2][3]);
            c[3][0] = fmaf(av.w, bw.x, c[3][0]); c[3][1] = fmaf(av.w, bw.y, c[3][1]);
            c[3][2] = fmaf(av.w, bw.z, c[3][2]); c[3][3] = fmaf(av.w, bw.w, c[3][3]);
        }
    }

    int gn = n0 + tx * 4;
    if (gn < N) {
#pragma unroll
        for (int i = 0; i < 4; i++) {
            int m = ty * 4 + i;
            *(float4*)(dst + (size_t)m * strideN + gn) =
                make_float4(c[i][0], c[i][1], c[i][2], c[i][3]);
        }
    }
}

// ---------------- GRU gate combine (sums gi/gh partials + biases) + logits finalize ----------------
__global__ __launch_bounds__(256) void h_update_kernel(
    float* __restrict__ outs, const float* __restrict__ bo,
    const float* __restrict__ b_ih, const float* __restrict__ b_hh,
    int t_fin, int do_gates)
{
    int idx = blockIdx.x * 256 + threadIdx.x;   // 32768
    if (t_fin >= 0) {
#pragma unroll
        for (int r = 0; r < 2; r++) {
            int e = idx + r * 32768;
            if (e < B * V) {
                int b = e / V, n = e - b * V;
                float sv = g_loP[0][e] + g_loP[1][e] + g_loP[2][e] + g_loP[3][e] + bo[n];
                outs[((size_t)b * TD + t_fin) * V + n] = sv;
            }
        }
    }
    if (do_gates) {
        int b = idx >> 9, j = idx & 511;
        int base = b * (3 * S);
        float gir = 0.f, giz = 0.f, gin = 0.f;
#pragma unroll
        for (int sl = 0; sl < 4; sl++) {
            gir += g_giP[sl][base + j];
            giz += g_giP[sl][base + 512 + j];
            gin += g_giP[sl][base + 1024 + j];
        }
        float ghr = 0.f, ghz = 0.f, ghn = 0.f;
#pragma unroll
        for (int sl = 0; sl < 2; sl++) {
            ghr += g_ghP[sl][base + j];
            ghz += g_ghP[sl][base + 512 + j];
            ghn += g_ghP[sl][base + 1024 + j];
        }
        float r = fast_sigmoid(gir + b_ih[j] + ghr + b_hh[j]);
        float z = fast_sigmoid(giz + b_ih[512 + j] + ghz + b_hh[512 + j]);
        float n = fast_tanh(gin + b_ih[1024 + j] + r * (ghn + b_hh[1024 + j]));
        float h = g_h[idx];
        g_h[idx] = (1.0f - z) * n + z * h;
    }
}

// ---------------- attention scores with f32x2: fused conv + tanh + v-dot ----------------
// 256 threads, each owns s-pair (2*tid, 2*tid+1), TT=16 t's per block.
__global__ __launch_bounds__(256, 2) void scores_kernel(const float* __restrict__ v_vec) {
    const int b = blockIdx.y;
    const int t0 = blockIdx.x * TT;
    const int tid = threadIdx.x;
    const int s0 = tid * 2;

    __shared__ float s_win[TT + KW - 1];   // 46
    __shared__ float s_red[8][TT + 1];

    if (tid < TT + KW - 1) {
        int t = t0 + tid - PAD;
        s_win[tid] = (t >= 0 && t < TF) ? g_w[b * TF + t] : 0.0f;
    }
    __syncthreads();

    // q pair = qbias + sum of 4 q partial slices
    u64 qv2 = *(const u64*)(g_qbias + s0);
#pragma unroll
    for (int sl = 0; sl < 4; sl++)
        qv2 = add2(qv2, *(const u64*)(&g_qP[sl][b * S + s0]));

    // conv filters for both s lanes (8B-aligned pair loads)
    u64 cw2[KW];
#pragma unroll
    for (int k = 0; k < KW; k++)
        cw2[k] = *(const u64*)(g_cwT + k * S + s0);

    // keys for both rows, init acc
    float k0[TT], k1[TT];
    const float* kp0 = g_keysT + ((size_t)b * S + s0) * TF + t0;
#pragma unroll
    for (int j = 0; j < TT; j += 4) {
        *(float4*)&k0[j] = *(const float4*)(kp0 + j);
        *(float4*)&k1[j] = *(const float4*)(kp0 + TF + j);
    }
    u64 acc[TT];
#pragma unroll
    for (int j = 0; j < TT; j++) acc[j] = add2(pack2(k0[j], k1[j]), qv2);

    // diagonal-ordered conv: one broadcast per window element, packed FMA2
#pragma unroll
    for (int i = 0; i < TT + KW - 1; i++) {
        u64 wv2 = pack2(s_win[i], s_win[i]);
#pragma unroll
        for (int j = 0; j < TT; j++) {
            int k = i - j;
            if (k >= 0 && k < KW) acc[j] = fma2(cw2[k], wv2, acc[j]);
        }
    }

    // tanh both lanes, weight by v, reduce over s
    float2 vv = *(const float2*)(v_vec + s0);
#pragma unroll
    for (int j = 0; j < TT; j++) {
        float a0, a1; unpack2(acc[j], a0, a1);
        float cv = vv.x * fast_tanh(a0) + vv.y * fast_tanh(a1);
#pragma unroll
        for (int off = 16; off > 0; off >>= 1)
            cv += __shfl_xor_sync(0xffffffffu, cv, off);
        if ((tid & 31) == 0) s_red[tid >> 5][j] = cv;
    }
    __syncthreads();
    if (tid < TT) {
        float sum = 0.0f;
#pragma unroll
        for (int w = 0; w < 8; w++) sum += s_red[w][tid];
        g_scores[b * TF + t0 + tid] = sum;
    }
}

// ---------------- softmax over Tf; writes g_w and ws output ----------------
__global__ __launch_bounds__(256) void softmax_kernel(float* __restrict__ ws, int t_step) {
    int b = blockIdx.x, tid = threadIdx.x;
    __shared__ float s_r[8];
    float vals[4];
    float m = -1e30f;
#pragma unroll
    for (int i = 0; i < 4; i++) {
        vals[i] = g_scores[b * TF + tid + i * 256];
        m = fmaxf(m, vals[i]);
    }
#pragma unroll
    for (int off = 16; off > 0; off >>= 1)
        m = fmaxf(m, __shfl_xor_sync(0xffffffffu, m, off));
    if ((tid & 31) == 0) s_r[tid >> 5] = m;
    __syncthreads();
    m = s_r[0];
#pragma unroll
    for (int w = 1; w < 8; w++) m = fmaxf(m, s_r[w]);
    __syncthreads();

    float sum = 0.0f;
#pragma unroll
    for (int i = 0; i < 4; i++) { vals[i] = __expf(vals[i] - m); sum += vals[i]; }
#pragma unroll
    for (int off = 16; off > 0; off >>= 1)
        sum += __shfl_xor_sync(0xffffffffu, sum, off);
    if ((tid & 31) == 0) s_r[tid >> 5] = sum;
    __syncthreads();
    float total = 0.0f;
#pragma unroll
    for (int w = 0; w < 8; w++) total += s_r[w];
    float inv = 1.0f / total;
#pragma unroll
    for (int i = 0; i < 4; i++) {
        int t = tid + i * 256;
        float wv = vals[i] * inv;
        g_w[b * TF + t] = wv;
        ws[((size_t)b * TD + t_step) * (size_t)TF + t] = wv;
    }
}

// ---------------- context: ctx[b,d] = sum_t w[b,t] * features[b,t,d] ----------------
__global__ __launch_bounds__(128) void ctx_kernel(const float* __restrict__ features) {
    int b = blockIdx.y;
    int d = blockIdx.x * 128 + threadIdx.x;
    __shared__ float s_w[TF];
    for (int i = threadIdx.x; i < TF; i += 128) s_w[i] = g_w[b * TF + i];
    __syncthreads();
    const float* f = features + (size_t)b * TF * S + d;
    float a0 = 0.f, a1 = 0.f, a2 = 0.f, a3 = 0.f;
#pragma unroll 2
    for (int t = 0; t < TF; t += 4) {
        a0 = fmaf(s_w[t + 0], f[(size_t)(t + 0) * S], a0);
        a1 = fmaf(s_w[t + 1], f[(size_t)(t + 1) * S], a1);
        a2 = fmaf(s_w[t + 2], f[(size_t)(t + 2) * S], a2);
        a3 = fmaf(s_w[t + 3], f[(size_t)(t + 3) * S], a3);
    }
    g_ctx[b * S + d] = (a0 + a1) + (a2 + a3);
}

// ---------------- launch ----------------
extern "C" void kernel_launch(void* const* d_in, const int* in_sizes, int n_in,
                              void* d_out, int out_size) {
    const int*   input    = (const int*)d_in[0];
    const float* features = (const float*)d_in[1];
    const float* emb      = (const float*)d_in[2];
    const float* W_ih     = (const float*)d_in[3];
    const float* W_hh     = (const float*)d_in[4];
    const float* b_ih     = (const float*)d_in[5];
    const float* b_hh     = (const float*)d_in[6];
    const float* Wq       = (const float*)d_in[7];
    const float* bq       = (const float*)d_in[8];
    const float* Wk       = (const float*)d_in[9];
    const float* bk       = (const float*)d_in[10];
    const float* conv_w   = (const float*)d_in[11];
    const float* conv_b   = (const float*)d_in[12];
    const float* v_vec    = (const float*)d_in[13];
    const float* Wo       = (const float*)d_in[14];
    const float* bo       = (const float*)d_in[15];

    float* outs = (float*)d_out;                        // [B, TD, V]
    float* ws   = outs + (size_t)B * TD * V;            // [B, TD, TF]

    init_kernel<<<(B * TF + 255) / 256, 256>>>();
    cw_transpose_kernel<<<(S * KW + 255) / 256, 256>>>(conv_w, bq, conv_b);
    keys_gemm_kernel<<<dim3((B * TF) / 64, S / 64), 256>>>(features, Wk, bk);

    // prologue: gate partials for t=0 (h0 = ctx0 = 0); grid.y=6 -> modes 0,1 only
    gemm64_kernel<<<dim3(24, 6), 256>>>(0, input, emb, W_ih, W_hh, Wq, Wo, 0);

    for (int t = 0; t < TD; ++t) {
        // finalize logits of t-1 (if any) + combine gate partials -> h_t
        h_update_kernel<<<128, 256>>>(outs, bo, b_ih, b_hh, t - 1, 1);
        // q partials (mode 2, 4 K-slices)
        gemm64_kernel<<<dim3(S / 64, 4), 256>>>(2, input, emb, W_ih, W_hh, Wq, Wo, t);
        scores_kernel<<<dim3(TF / TT, B), 256>>>(v_vec);
        softmax_kernel<<<B, 256>>>(ws, t);
        ctx_kernel<<<dim3(S / 128, B), 128>>>(features);
        if (t < TD - 1) {
            // combined: gates for t+1 (y 0..5) + logits partials for t (y 6..9)
            gemm64_kernel<<<dim3(24, 10), 256>>>(0, input, emb, W_ih, W_hh, Wq, Wo, t + 1);
        } else {
            // last step: logits partials only
            gemm64_kernel<<<dim3(16, 4), 256>>>(3, input, emb, W_ih, W_hh, Wq, Wo, t);
        }
    }
    // epilogue: finalize logits of final step
    h_update_kernel<<<128, 256>>>(outs, bo, b_ih, b_hh, TD - 1, 0);
}

// round 10
// speedup vs baseline: 1.3174x; 1.0974x over previous
#include <cuda_runtime.h>
#include <cuda_bf16.h>

#define B     64
#define S     512
#define TF    1024
#define TD    128
#define V     1000
#define KW    31
#define PAD   15
#define TT    16   // t-tile in scores kernel
#define NTILE 8    // t-tiles per scores block

typedef unsigned long long u64;

// ---------------- scratch (device globals; no allocation allowed) ----------------
__device__ float g_keysT[(size_t)B * S * TF];   // keys transposed: [b][s][t]
__device__ float g_h[B * S];
__device__ float g_ctx[B * S];
__device__ float g_w[B * TF];
__device__ float g_scores[B * TF];
__device__ float g_cwT[KW * S];                 // conv filters transposed: [k][s]
__device__ float g_qbias[S];                    // bq + conv_b
// split-K partial buffers (written whole each step; no zeroing needed)
__device__ float g_giP[4][B * 3 * S];
__device__ float g_ghP[2][B * 3 * S];
__device__ float g_qP[4][B * S];
__device__ float g_loP[4][B * V];

// ---------------- f32x2 helpers ----------------
__device__ __forceinline__ u64 pack2(float lo, float hi) {
    u64 r; asm("mov.b64 %0, {%1,%2};" : "=l"(r) : "f"(lo), "f"(hi)); return r;
}
__device__ __forceinline__ void unpack2(u64 v, float& lo, float& hi) {
    asm("mov.b64 {%0,%1}, %2;" : "=f"(lo), "=f"(hi) : "l"(v));
}
__device__ __forceinline__ u64 add2(u64 a, u64 b) {
    u64 r; asm("add.rn.f32x2 %0, %1, %2;" : "=l"(r) : "l"(a), "l"(b)); return r;
}
__device__ __forceinline__ u64 fma2(u64 a, u64 b, u64 c) {
    u64 r; asm("fma.rn.f32x2 %0, %1, %2, %3;" : "=l"(r) : "l"(a), "l"(b), "l"(c)); return r;
}

__device__ __forceinline__ float fast_tanh(float x) {
    float e = __expf(2.0f * x);
    return 1.0f - __fdividef(2.0f, e + 1.0f);
}
__device__ __forceinline__ float fast_sigmoid(float x) {
    return __fdividef(1.0f, 1.0f + __expf(-x));
}

// ---------------- init: zero recurrent state ----------------
__global__ void init_kernel() {
    int idx = blockIdx.x * 256 + threadIdx.x;
    if (idx < B * S) { g_h[idx] = 0.0f; g_ctx[idx] = 0.0f; }
    if (idx < B * TF) g_w[idx] = 0.0f;
}

// ---------------- transpose conv filters + qbias ----------------
__global__ void cw_transpose_kernel(const float* __restrict__ conv_w,
                                    const float* __restrict__ bq,
                                    const float* __restrict__ conv_b) {
    int idx = blockIdx.x * 256 + threadIdx.x;
    if (idx < S * KW) {
        int s = idx / KW, k = idx % KW;
        g_cwT[k * S + s] = conv_w[idx];
    }
    if (idx < S) g_qbias[idx] = bq[idx] + conv_b[idx];
}

// ---------------- keys precompute: keysT[b][n][t] = sum_k F[b,t,k]*Wk[n,k] + bk[n] ----------------
__global__ __launch_bounds__(256) void keys_gemm_kernel(
    const float* __restrict__ features, const float* __restrict__ Wk,
    const float* __restrict__ bk)
{
    __shared__ float As[16][68];
    __shared__ float Bs[16][68];
    int tid = threadIdx.x;
    int m0 = blockIdx.x * 64, n0 = blockIdx.y * 64;
    int lr = tid & 63, lk = tid >> 6;
    int tx = tid & 15, ty = tid >> 4;
    float c[4][4] = {};

    for (int k0 = 0; k0 < S; k0 += 16) {
        float4 a = *(const float4*)(features + (size_t)(m0 + lr) * S + k0 + lk * 4);
        float4 bv = *(const float4*)(Wk + (size_t)(n0 + lr) * S + k0 + lk * 4);
        __syncthreads();
        As[lk * 4 + 0][lr] = a.x;  As[lk * 4 + 1][lr] = a.y;
        As[lk * 4 + 2][lr] = a.z;  As[lk * 4 + 3][lr] = a.w;
        Bs[lk * 4 + 0][lr] = bv.x; Bs[lk * 4 + 1][lr] = bv.y;
        Bs[lk * 4 + 2][lr] = bv.z; Bs[lk * 4 + 3][lr] = bv.w;
        __syncthreads();
#pragma unroll
        for (int k = 0; k < 16; k++) {
            float4 av = *(const float4*)&As[k][ty * 4];
            float4 bw = *(const float4*)&Bs[k][tx * 4];
            c[0][0] = fmaf(av.x, bw.x, c[0][0]); c[0][1] = fmaf(av.x, bw.y, c[0][1]);
            c[0][2] = fmaf(av.x, bw.z, c[0][2]); c[0][3] = fmaf(av.x, bw.w, c[0][3]);
            c[1][0] = fmaf(av.y, bw.x, c[1][0]); c[1][1] = fmaf(av.y, bw.y, c[1][1]);
            c[1][2] = fmaf(av.y, bw.z, c[1][2]); c[1][3] = fmaf(av.y, bw.w, c[1][3]);
            c[2][0] = fmaf(av.z, bw.x, c[2][0]); c[2][1] = fmaf(av.z, bw.y, c[2][1]);
            c[2][2] = fmaf(av.z, bw.z, c[2][2]); c[2][3] = fmaf(av.z, bw.w, c[2][3]);
            c[3][0] = fmaf(av.w, bw.x, c[3][0]); c[3][1] = fmaf(av.w, bw.y, c[3][1]);
            c[3][2] = fmaf(av.w, bw.z, c[3][2]); c[3][3] = fmaf(av.w, bw.w, c[3][3]);
        }
    }
    int bb = m0 >> 10;
    int tbase = (m0 & 1023) + ty * 4;
#pragma unroll
    for (int j = 0; j < 4; j++) {
        int n = n0 + tx * 4 + j;
        float bias = bk[n];
        float* dst = g_keysT + ((size_t)bb * S + n) * TF + tbase;
#pragma unroll
        for (int i = 0; i < 4; i++) dst[i] = c[i][j] + bias;
    }
}

// ---------------- split-K skinny GEMM: 64x64 tile, 4x4/thread, partials, NO bias ----------------
__global__ __launch_bounds__(256) void gemm64_kernel(
    int mb,
    const int* __restrict__ input_ids, const float* __restrict__ emb,
    const float* __restrict__ W_ih, const float* __restrict__ W_hh,
    const float* __restrict__ Wq, const float* __restrict__ Wo,
    int t_gates)
{
    int by = blockIdx.y;
    int mode, sl;
    if (mb == 2)      { mode = 2; sl = by; }
    else if (mb == 3) { mode = 3; sl = by; }
    else {
        if (by < 4)      { mode = 0; sl = by; }
        else if (by < 6) { mode = 1; sl = by - 4; }
        else             { mode = 3; sl = by - 6; }
    }

    int N, Ktot, Ksl, strideN;
    const float* Bmat;
    float* dst;
    if (mode == 0)      { N = 3*S; Ktot = 1024; Ksl = 256; Bmat = W_ih; dst = g_giP[sl]; strideN = 3*S; }
    else if (mode == 1) { N = 3*S; Ktot = 512;  Ksl = 256; Bmat = W_hh; dst = g_ghP[sl]; strideN = 3*S; }
    else if (mode == 2) { N = S;   Ktot = 512;  Ksl = 128; Bmat = Wq;   dst = g_qP[sl];  strideN = S; }
    else                { N = V;   Ktot = 1024; Ksl = 256; Bmat = Wo;   dst = g_loP[sl]; strideN = V; }

    int n0 = blockIdx.x * 64;
    if (n0 >= N) return;

    __shared__ float As[16][68];
    __shared__ float Bs[16][68];
    __shared__ int s_idx[64];

    int tid = threadIdx.x;
    if (mode == 0 && tid < 64) s_idx[tid] = input_ids[tid * TD + t_gates];
    __syncthreads();

    int lr = tid & 63, lk = tid >> 6;
    int tx = tid & 15, ty = tid >> 4;
    float c[4][4] = {};

    for (int kc = 0; kc < Ksl; kc += 16) {
        int kb = sl * Ksl + kc + lk * 4;
        const float* ap;
        if (mode == 0) {
            if (kb < 512) ap = emb + (size_t)s_idx[lr] * S + kb;
            else          ap = g_ctx + lr * S + (kb - 512);
        } else if (mode == 3) {
            if (kb < 512) ap = g_h + lr * S + kb;
            else          ap = g_ctx + lr * S + (kb - 512);
        } else {
            ap = g_h + lr * S + kb;
        }
        float4 a = *(const float4*)ap;

        int gn = n0 + lr;
        float4 bv = make_float4(0.f, 0.f, 0.f, 0.f);
        if (gn < N) bv = *(const float4*)(Bmat + (size_t)gn * Ktot + kb);

        __syncthreads();
        As[lk * 4 + 0][lr] = a.x;  As[lk * 4 + 1][lr] = a.y;
        As[lk * 4 + 2][lr] = a.z;  As[lk * 4 + 3][lr] = a.w;
        Bs[lk * 4 + 0][lr] = bv.x; Bs[lk * 4 + 1][lr] = bv.y;
        Bs[lk * 4 + 2][lr] = bv.z; Bs[lk * 4 + 3][lr] = bv.w;
        __syncthreads();
#pragma unroll
        for (int k = 0; k < 16; k++) {
            float4 av = *(const float4*)&As[k][ty * 4];
            float4 bw = *(const float4*)&Bs[k][tx * 4];
            c[0][0] = fmaf(av.x, bw.x, c[0][0]); c[0][1] = fmaf(av.x, bw.y, c[0][1]);
            c[0][2] = fmaf(av.x, bw.z, c[0][2]); c[0][3] = fmaf(av.x, bw.w, c[0][3]);
            c[1][0] = fmaf(av.y, bw.x, c[1][0]); c[1][1] = fmaf(av.y, bw.y, c[1][1]);
            c[1][2] = fmaf(av.y, bw.z, c[1][2]); c[1][3] = fmaf(av.y, bw.w, c[1][3]);
            c[2][0] = fmaf(av.z, bw.x, c[2][0]); c[2][1] = fmaf(av.z, bw.y, c[2][1]);
            c[2][2] = fmaf(av.z, bw.z, c[2][2]); c[2][3] = fmaf(av.z, bw.w, c[2][3]);
            c[3][0] = fmaf(av.w, bw.x, c[3][0]); c[3][1] = fmaf(av.w, bw.y, c[3][1]);
            c[3][2] = fmaf(av.w, bw.z, c[3][2]); c[3][3] = fmaf(av.w, bw.w, c[3][3]);
        }
    }

    int gn = n0 + tx * 4;
    if (gn < N) {
#pragma unroll
        for (int i = 0; i < 4; i++) {
            int m = ty * 4 + i;
            *(float4*)(dst + (size_t)m * strideN + gn) =
                make_float4(c[i][0], c[i][1], c[i][2], c[i][3]);
        }
    }
}

// ---------------- GRU gate combine (sums partials + biases) + logits finalize ----------------
__global__ __launch_bounds__(256) void h_update_kernel(
    float* __restrict__ outs, const float* __restrict__ bo,
    const float* __restrict__ b_ih, const float* __restrict__ b_hh,
    int t_fin, int do_gates)
{
    int idx = blockIdx.x * 256 + threadIdx.x;   // 32768
    if (t_fin >= 0) {
#pragma unroll
        for (int r = 0; r < 2; r++) {
            int e = idx + r * 32768;
            if (e < B * V) {
                int b = e / V, n = e - b * V;
                float sv = g_loP[0][e] + g_loP[1][e] + g_loP[2][e] + g_loP[3][e] + bo[n];
                outs[((size_t)b * TD + t_fin) * V + n] = sv;
            }
        }
    }
    if (do_gates) {
        int b = idx >> 9, j = idx & 511;
        int base = b * (3 * S);
        float gir = 0.f, giz = 0.f, gin = 0.f;
#pragma unroll
        for (int sl = 0; sl < 4; sl++) {
            gir += g_giP[sl][base + j];
            giz += g_giP[sl][base + 512 + j];
            gin += g_giP[sl][base + 1024 + j];
        }
        float ghr = 0.f, ghz = 0.f, ghn = 0.f;
#pragma unroll
        for (int sl = 0; sl < 2; sl++) {
            ghr += g_ghP[sl][base + j];
            ghz += g_ghP[sl][base + 512 + j];
            ghn += g_ghP[sl][base + 1024 + j];
        }
        float r = fast_sigmoid(gir + b_ih[j] + ghr + b_hh[j]);
        float z = fast_sigmoid(giz + b_ih[512 + j] + ghz + b_hh[512 + j]);
        float n = fast_tanh(gin + b_ih[1024 + j] + r * (ghn + b_hh[1024 + j]));
        float h = g_h[idx];
        g_h[idx] = (1.0f - z) * n + z * h;
    }
}

// ---------------- attention scores: persistent over NTILE t-tiles ----------------
// block (tg, b): handles t in [tg*128, tg*128+128). 256 threads, each owns s-pair.
// Filters/q/v loaded ONCE per block (kills the per-tile 63KB reload).
__global__ __launch_bounds__(256, 2) void scores_kernel(const float* __restrict__ v_vec) {
    const int b = blockIdx.y;
    const int tg = blockIdx.x;
    const int tid = threadIdx.x;
    const int s0 = tid * 2;

    __shared__ float s_win[TT + KW - 1];   // 46
    __shared__ float s_red[8][TT + 1];

    // persistent per-block state
    u64 qv2 = *(const u64*)(g_qbias + s0);
#pragma unroll
    for (int sl = 0; sl < 4; sl++)
        qv2 = add2(qv2, *(const u64*)(&g_qP[sl][b * S + s0]));

    u64 cw2[KW];
#pragma unroll
    for (int k = 0; k < KW; k++)
        cw2[k] = *(const u64*)(g_cwT + k * S + s0);

    float2 vv = *(const float2*)(v_vec + s0);
    const float* kp0 = g_keysT + ((size_t)b * S + s0) * TF;

    for (int tt = 0; tt < NTILE; tt++) {
        const int t0 = tg * (NTILE * TT) + tt * TT;

        if (tid < TT + KW - 1) {
            int t = t0 + tid - PAD;
            s_win[tid] = (t >= 0 && t < TF) ? g_w[b * TF + t] : 0.0f;
        }
        __syncthreads();

        // keys for both rows packed straight into acc (no staging arrays)
        u64 acc[TT];
#pragma unroll
        for (int j = 0; j < TT; j += 4) {
            float4 a = *(const float4*)(kp0 + t0 + j);
            float4 c = *(const float4*)(kp0 + TF + t0 + j);
            acc[j + 0] = add2(pack2(a.x, c.x), qv2);
            acc[j + 1] = add2(pack2(a.y, c.y), qv2);
            acc[j + 2] = add2(pack2(a.z, c.z), qv2);
            acc[j + 3] = add2(pack2(a.w, c.w), qv2);
        }

        // diagonal-ordered conv: one broadcast per window element, packed FMA2
#pragma unroll
        for (int i = 0; i < TT + KW - 1; i++) {
            u64 wv2 = pack2(s_win[i], s_win[i]);
#pragma unroll
            for (int j = 0; j < TT; j++) {
                int k = i - j;
                if (k >= 0 && k < KW) acc[j] = fma2(cw2[k], wv2, acc[j]);
            }
        }

        // tanh both lanes, weight by v, reduce over s
#pragma unroll
        for (int j = 0; j < TT; j++) {
            float a0, a1; unpack2(acc[j], a0, a1);
            float cv = vv.x * fast_tanh(a0) + vv.y * fast_tanh(a1);
#pragma unroll
            for (int off = 16; off > 0; off >>= 1)
                cv += __shfl_xor_sync(0xffffffffu, cv, off);
            if ((tid & 31) == 0) s_red[tid >> 5][j] = cv;
        }
        __syncthreads();
        if (tid < TT) {
            float sum = 0.0f;
#pragma unroll
            for (int w = 0; w < 8; w++) sum += s_red[w][tid];
            g_scores[b * TF + t0 + tid] = sum;
        }
    }
}

// ---------------- fused softmax + context ----------------
// grid (2, B), 256 threads. Both blocks per b recompute the row softmax
// (4KB, L2-hot, deterministic); block x==0 also writes g_w and ws.
// Then each block accumulates ctx for its 256 d's.
__global__ __launch_bounds__(256) void ctxsm_kernel(
    const float* __restrict__ features, float* __restrict__ ws, int t_step)
{
    int b = blockIdx.y, tid = threadIdx.x;
    __shared__ float s_w[TF];
    __shared__ float s_r[8];

    float vals[4];
    float m = -1e30f;
#pragma unroll
    for (int i = 0; i < 4; i++) {
        vals[i] = g_scores[b * TF + tid + i * 256];
        m = fmaxf(m, vals[i]);
    }
#pragma unroll
    for (int off = 16; off > 0; off >>= 1)
        m = fmaxf(m, __shfl_xor_sync(0xffffffffu, m, off));
    if ((tid & 31) == 0) s_r[tid >> 5] = m;
    __syncthreads();
    m = s_r[0];
#pragma unroll
    for (int w = 1; w < 8; w++) m = fmaxf(m, s_r[w]);
    __syncthreads();

    float sum = 0.0f;
#pragma unroll
    for (int i = 0; i < 4; i++) { vals[i] = __expf(vals[i] - m); sum += vals[i]; }
#pragma unroll
    for (int off = 16; off > 0; off >>= 1)
        sum += __shfl_xor_sync(0xffffffffu, sum, off);
    if ((tid & 31) == 0) s_r[tid >> 5] = sum;
    __syncthreads();
    float total = 0.0f;
#pragma unroll
    for (int w = 0; w < 8; w++) total += s_r[w];
    float inv = __fdividef(1.0f, total);
#pragma unroll
    for (int i = 0; i < 4; i++) {
        int t = tid + i * 256;
        float wv = vals[i] * inv;
        s_w[t] = wv;
        if (blockIdx.x == 0) {
            g_w[b * TF + t] = wv;
            ws[((size_t)b * TD + t_step) * (size_t)TF + t] = wv;
        }
    }
    __syncthreads();

    // ctx for this block's 256 d's
    int d = blockIdx.x * 256 + tid;
    const float* f = features + (size_t)b * TF * S + d;
    float a0 = 0.f, a1 = 0.f, a2 = 0.f, a3 = 0.f;
#pragma unroll 2
    for (int t = 0; t < TF; t += 4) {
        a0 = fmaf(s_w[t + 0], f[(size_t)(t + 0) * S], a0);
        a1 = fmaf(s_w[t + 1], f[(size_t)(t + 1) * S], a1);
        a2 = fmaf(s_w[t + 2], f[(size_t)(t + 2) * S], a2);
        a3 = fmaf(s_w[t + 3], f[(size_t)(t + 3) * S], a3);
    }
    g_ctx[b * S + d] = (a0 + a1) + (a2 + a3);
}

// ---------------- launch ----------------
extern "C" void kernel_launch(void* const* d_in, const int* in_sizes, int n_in,
                              void* d_out, int out_size) {
    const int*   input    = (const int*)d_in[0];
    const float* features = (const float*)d_in[1];
    const float* emb      = (const float*)d_in[2];
    const float* W_ih     = (const float*)d_in[3];
    const float* W_hh     = (const float*)d_in[4];
    const float* b_ih     = (const float*)d_in[5];
    const float* b_hh     = (const float*)d_in[6];
    const float* Wq       = (const float*)d_in[7];
    const float* bq       = (const float*)d_in[8];
    const float* Wk       = (const float*)d_in[9];
    const float* bk       = (const float*)d_in[10];
    const float* conv_w   = (const float*)d_in[11];
    const float* conv_b   = (const float*)d_in[12];
    const float* v_vec    = (const float*)d_in[13];
    const float* Wo       = (const float*)d_in[14];
    const float* bo       = (const float*)d_in[15];

    float* outs = (float*)d_out;                        // [B, TD, V]
    float* ws   = outs + (size_t)B * TD * V;            // [B, TD, TF]

    init_kernel<<<(B * TF + 255) / 256, 256>>>();
    cw_transpose_kernel<<<(S * KW + 255) / 256, 256>>>(conv_w, bq, conv_b);
    keys_gemm_kernel<<<dim3((B * TF) / 64, S / 64), 256>>>(features, Wk, bk);

    // prologue: gate partials for t=0 (h0 = ctx0 = 0)
    gemm64_kernel<<<dim3(24, 6), 256>>>(0, input, emb, W_ih, W_hh, Wq, Wo, 0);

    for (int t = 0; t < TD; ++t) {
        // finalize logits of t-1 (if any) + combine gate partials -> h_t
        h_update_kernel<<<128, 256>>>(outs, bo, b_ih, b_hh, t - 1, 1);
        // q partials (mode 2, 4 K-slices)
        gemm64_kernel<<<dim3(S / 64, 4), 256>>>(2, input, emb, W_ih, W_hh, Wq, Wo, t);
        scores_kernel<<<dim3(TF / (TT * NTILE), B), 256>>>(v_vec);
        ctxsm_kernel<<<dim3(2, B), 256>>>(features, ws, t);
        if (t < TD - 1) {
            gemm64_kernel<<<dim3(24, 10), 256>>>(0, input, emb, W_ih, W_hh, Wq, Wo, t + 1);
        } else {
            gemm64_kernel<<<dim3(16, 4), 256>>>(3, input, emb, W_ih, W_hh, Wq, Wo, t);
        }
    }
    // epilogue: finalize logits of final step
    h_update_kernel<<<128, 256>>>(outs, bo, b_ih, b_hh, TD - 1, 0);
}

// round 13
// speedup vs baseline: 1.7007x; 1.2910x over previous
#include <cuda_runtime.h>
#include <cuda_bf16.h>
#include <cuda_fp16.h>

#define B     64
#define S     512
#define TF    1024
#define TD    128
#define V     1000
#define KW    31
#define PAD   15
#define TT    16   // t-tile in scores kernel
#define NTILE 8    // t-tiles per scores block

typedef unsigned long long u64;

// ---------------- scratch (device globals; no allocation allowed) ----------------
__device__ __half g_keysTh[(size_t)B * S * TF];  // keys transposed fp16: [b][s][t]
__device__ __half g_featH[(size_t)B * TF * S];   // features fp16 copy: [b][t][d]
__device__ float g_h[B * S];
__device__ float g_ctxP[2][B * S];              // ctx t-half partials
__device__ float g_w[B * TF];
__device__ float g_scores[B * TF];
__device__ float g_cwT[KW * S];                 // conv filters transposed: [k][s]
__device__ float g_qbias[S];                    // bq + conv_b
// split-K partial buffers (written whole each step; no zeroing needed)
__device__ float g_giP[8][B * 3 * S];
__device__ float g_ghP[4][B * 3 * S];
__device__ float g_qP[8][B * S];
__device__ float g_loP[8][B * V];

// ---------------- f32x2 / fp16 helpers ----------------
__device__ __forceinline__ u64 pack2(float lo, float hi) {
    u64 r; asm("mov.b64 %0, {%1,%2};" : "=l"(r) : "f"(lo), "f"(hi)); return r;
}
__device__ __forceinline__ void unpack2(u64 v, float& lo, float& hi) {
    asm("mov.b64 {%0,%1}, %2;" : "=f"(lo), "=f"(hi) : "l"(v));
}
__device__ __forceinline__ u64 add2(u64 a, u64 b) {
    u64 r; asm("add.rn.f32x2 %0, %1, %2;" : "=l"(r) : "l"(a), "l"(b)); return r;
}
__device__ __forceinline__ u64 fma2(u64 a, u64 b, u64 c) {
    u64 r; asm("fma.rn.f32x2 %0, %1, %2, %3;" : "=l"(r) : "l"(a), "l"(b), "l"(c)); return r;
}
__device__ __forceinline__ void h2f(unsigned u, float& lo, float& hi) {
    __half2 h = *reinterpret_cast<__half2*>(&u);
    float2 f = __half22float2(h);
    lo = f.x; hi = f.y;
}

__device__ __forceinline__ float fast_tanh(float x) {
    float e = __expf(2.0f * x);
    return 1.0f - __fdividef(2.0f, e + 1.0f);
}
__device__ __forceinline__ float fast_sigmoid(float x) {
    return __fdividef(1.0f, 1.0f + __expf(-x));
}

// ---------------- init: zero recurrent state ----------------
__global__ void init_kernel() {
    int idx = blockIdx.x * 256 + threadIdx.x;
    if (idx < B * S) { g_h[idx] = 0.0f; g_ctxP[0][idx] = 0.0f; g_ctxP[1][idx] = 0.0f; }
    if (idx < B * TF) g_w[idx] = 0.0f;
}

// ---------------- features -> fp16 copy (one-time) ----------------
__global__ __launch_bounds__(256) void feat_convert_kernel(const float* __restrict__ features) {
    size_t idx = (size_t)blockIdx.x * 256 + threadIdx.x;   // over elements/4
    float4 v = *(const float4*)(features + idx * 4);
    __half2 lo = __floats2half2_rn(v.x, v.y);
    __half2 hi = __floats2half2_rn(v.z, v.w);
    uint2 o;
    o.x = *(unsigned*)&lo; o.y = *(unsigned*)&hi;
    *(uint2*)(g_featH + idx * 4) = o;
}

// ---------------- transpose conv filters + qbias ----------------
__global__ void cw_transpose_kernel(const float* __restrict__ conv_w,
                                    const float* __restrict__ bq,
                                    const float* __restrict__ conv_b) {
    int idx = blockIdx.x * 256 + threadIdx.x;
    if (idx < S * KW) {
        int s = idx / KW, k = idx % KW;
        g_cwT[k * S + s] = conv_w[idx];
    }
    if (idx < S) g_qbias[idx] = bq[idx] + conv_b[idx];
}

// ---------------- keys precompute -> fp16 keysT ----------------
__global__ __launch_bounds__(256) void keys_gemm_kernel(
    const float* __restrict__ features, const float* __restrict__ Wk,
    const float* __restrict__ bk)
{
    __shared__ float As[16][68];
    __shared__ float Bs[16][68];
    int tid = threadIdx.x;
    int m0 = blockIdx.x * 64, n0 = blockIdx.y * 64;
    int lr = tid & 63, lk = tid >> 6;
    int tx = tid & 15, ty = tid >> 4;
    float c[4][4] = {};

    for (int k0 = 0; k0 < S; k0 += 16) {
        float4 a = *(const float4*)(features + (size_t)(m0 + lr) * S + k0 + lk * 4);
        float4 bv = *(const float4*)(Wk + (size_t)(n0 + lr) * S + k0 + lk * 4);
        __syncthreads();
        As[lk * 4 + 0][lr] = a.x;  As[lk * 4 + 1][lr] = a.y;
        As[lk * 4 + 2][lr] = a.z;  As[lk * 4 + 3][lr] = a.w;
        Bs[lk * 4 + 0][lr] = bv.x; Bs[lk * 4 + 1][lr] = bv.y;
        Bs[lk * 4 + 2][lr] = bv.z; Bs[lk * 4 + 3][lr] = bv.w;
        __syncthreads();
#pragma unroll
        for (int k = 0; k < 16; k++) {
            float4 av = *(const float4*)&As[k][ty * 4];
            float4 bw = *(const float4*)&Bs[k][tx * 4];
            c[0][0] = fmaf(av.x, bw.x, c[0][0]); c[0][1] = fmaf(av.x, bw.y, c[0][1]);
            c[0][2] = fmaf(av.x, bw.z, c[0][2]); c[0][3] = fmaf(av.x, bw.w, c[0][3]);
            c[1][0] = fmaf(av.y, bw.x, c[1][0]); c[1][1] = fmaf(av.y, bw.y, c[1][1]);
            c[1][2] = fmaf(av.y, bw.z, c[1][2]); c[1][3] = fmaf(av.y, bw.w, c[1][3]);
            c[2][0] = fmaf(av.z, bw.x, c[2][0]); c[2][1] = fmaf(av.z, bw.y, c[2][1]);
            c[2][2] = fmaf(av.z, bw.z, c[2][2]); c[2][3] = fmaf(av.z, bw.w, c[2][3]);
            c[3][0] = fmaf(av.w, bw.x, c[3][0]); c[3][1] = fmaf(av.w, bw.y, c[3][1]);
            c[3][2] = fmaf(av.w, bw.z, c[3][2]); c[3][3] = fmaf(av.w, bw.w, c[3][3]);
        }
    }
    int bb = m0 >> 10;
    int tbase = (m0 & 1023) + ty * 4;
#pragma unroll
    for (int j = 0; j < 4; j++) {
        int n = n0 + tx * 4 + j;
        float bias = bk[n];
        __half* dst = g_keysTh + ((size_t)bb * S + n) * TF + tbase;
        __half2 p0 = __floats2half2_rn(c[0][j] + bias, c[1][j] + bias);
        __half2 p1 = __floats2half2_rn(c[2][j] + bias, c[3][j] + bias);
        *(__half2*)(dst) = p0;
        *(__half2*)(dst + 2) = p1;
    }
}

// ---------------- split-K skinny GEMM: 64x64 tile, 4x4/thread, partials, NO bias ----------------
// mode 0: gi partials  = x @ W_ih^T   (Ktot=1024, Ksl=128, 8 slices, N=1536)
// mode 1: gh partials  = h @ W_hh^T   (Ktot=512,  Ksl=128, 4 slices, N=1536)
// mode 2: q  partials  = h @ Wq^T     (Ktot=512,  Ksl=64,  8 slices, N=512)
// mode 3: logits part. = [h|ctx]@Wo^T (Ktot=1024, Ksl=128, 8 slices, N=1000)
// mb=0: by<8 -> mode0 sl=by; by<12 -> mode1 sl=by-8; else mode3 sl=by-12
// mb=2: mode2 sl=by.   mb=3: mode3 sl=by.
__global__ __launch_bounds__(256) void gemm64_kernel(
    int mb,
    const int* __restrict__ input_ids, const float* __restrict__ emb,
    const float* __restrict__ W_ih, const float* __restrict__ W_hh,
    const float* __restrict__ Wq, const float* __restrict__ Wo,
    int t_gates)
{
    int by = blockIdx.y;
    int mode, sl;
    if (mb == 2)      { mode = 2; sl = by; }
    else if (mb == 3) { mode = 3; sl = by; }
    else {
        if (by < 8)       { mode = 0; sl = by; }
        else if (by < 12) { mode = 1; sl = by - 8; }
        else              { mode = 3; sl = by - 12; }
    }

    int N, Ktot, Ksl, strideN;
    const float* Bmat;
    float* dst;
    if (mode == 0)      { N = 3*S; Ktot = 1024; Ksl = 128; Bmat = W_ih; dst = g_giP[sl]; strideN = 3*S; }
    else if (mode == 1) { N = 3*S; Ktot = 512;  Ksl = 128; Bmat = W_hh; dst = g_ghP[sl]; strideN = 3*S; }
    else if (mode == 2) { N = S;   Ktot = 512;  Ksl = 64;  Bmat = Wq;   dst = g_qP[sl];  strideN = S; }
    else                { N = V;   Ktot = 1024; Ksl = 128; Bmat = Wo;   dst = g_loP[sl]; strideN = V; }

    int n0 = blockIdx.x * 64;
    if (n0 >= N) return;

    __shared__ float As[16][68];
    __shared__ float Bs[16][68];
    __shared__ int s_idx[64];

    int tid = threadIdx.x;
    if (mode == 0 && tid < 64) s_idx[tid] = input_ids[tid * TD + t_gates];
    __syncthreads();

    int lr = tid & 63, lk = tid >> 6;
    int tx = tid & 15, ty = tid >> 4;
    float c[4][4] = {};

    for (int kc = 0; kc < Ksl; kc += 16) {
        int kb = sl * Ksl + kc + lk * 4;
        float4 a;
        if (mode == 0) {
            if (kb < 512) a = *(const float4*)(emb + (size_t)s_idx[lr] * S + kb);
            else {
                int off = lr * S + (kb - 512);
                float4 p0 = *(const float4*)(g_ctxP[0] + off);
                float4 p1 = *(const float4*)(g_ctxP[1] + off);
                a = make_float4(p0.x + p1.x, p0.y + p1.y, p0.z + p1.z, p0.w + p1.w);
            }
        } else if (mode == 3) {
            if (kb < 512) a = *(const float4*)(g_h + lr * S + kb);
            else {
                int off = lr * S + (kb - 512);
                float4 p0 = *(const float4*)(g_ctxP[0] + off);
                float4 p1 = *(const float4*)(g_ctxP[1] + off);
                a = make_float4(p0.x + p1.x, p0.y + p1.y, p0.z + p1.z, p0.w + p1.w);
            }
        } else {
            a = *(const float4*)(g_h + lr * S + kb);
        }

        int gn = n0 + lr;
        float4 bv = make_float4(0.f, 0.f, 0.f, 0.f);
        if (gn < N) bv = *(const float4*)(Bmat + (size_t)gn * Ktot + kb);

        __syncthreads();
        As[lk * 4 + 0][lr] = a.x;  As[lk * 4 + 1][lr] = a.y;
        As[lk * 4 + 2][lr] = a.z;  As[lk * 4 + 3][lr] = a.w;
        Bs[lk * 4 + 0][lr] = bv.x; Bs[lk * 4 + 1][lr] = bv.y;
        Bs[lk * 4 + 2][lr] = bv.z; Bs[lk * 4 + 3][lr] = bv.w;
        __syncthreads();
#pragma unroll
        for (int k = 0; k < 16; k++) {
            float4 av = *(const float4*)&As[k][ty * 4];
            float4 bw = *(const float4*)&Bs[k][tx * 4];
            c[0][0] = fmaf(av.x, bw.x, c[0][0]); c[0][1] = fmaf(av.x, bw.y, c[0][1]);
            c[0][2] = fmaf(av.x, bw.z, c[0][2]); c[0][3] = fmaf(av.x, bw.w, c[0][3]);
            c[1][0] = fmaf(av.y, bw.x, c[1][0]); c[1][1] = fmaf(av.y, bw.y, c[1][1]);
            c[1][2] = fmaf(av.y, bw.z, c[1][2]); c[1][3] = fmaf(av.y, bw.w, c[1][3]);
            c[2][0] = fmaf(av.z, bw.x, c[2][0]); c[2][1] = fmaf(av.z, bw.y, c[2][1]);
            c[2][2] = fmaf(av.z, bw.z, c[2][2]); c[2][3] = fmaf(av.z, bw.w, c[2][3]);
            c[3][0] = fmaf(av.w, bw.x, c[3][0]); c[3][1] = fmaf(av.w, bw.y, c[3][1]);
            c[3][2] = fmaf(av.w, bw.z, c[3][2]); c[3][3] = fmaf(av.w, bw.w, c[3][3]);
        }
    }

    int gn = n0 + tx * 4;
    if (gn < N) {
#pragma unroll
        for (int i = 0; i < 4; i++) {
            int m = ty * 4 + i;
            *(float4*)(dst + (size_t)m * strideN + gn) =
                make_float4(c[i][0], c[i][1], c[i][2], c[i][3]);
        }
    }
}

// ---------------- GRU gate combine (sums partials + biases) + logits finalize ----------------
__global__ __launch_bounds__(256) void h_update_kernel(
    float* __restrict__ outs, const float* __restrict__ bo,
    const float* __restrict__ b_ih, const float* __restrict__ b_hh,
    int t_fin, int do_gates)
{
    int idx = blockIdx.x * 256 + threadIdx.x;   // 32768
    if (t_fin >= 0) {
#pragma unroll
        for (int r = 0; r < 2; r++) {
            int e = idx + r * 32768;
            if (e < B * V) {
                int b = e / V, n = e - b * V;
                float sv = bo[n];
#pragma unroll
                for (int sl = 0; sl < 8; sl++) sv += g_loP[sl][e];
                outs[((size_t)b * TD + t_fin) * V + n] = sv;
            }
        }
    }
    if (do_gates) {
        int b = idx >> 9, j = idx & 511;
        int base = b * (3 * S);
        float gir = 0.f, giz = 0.f, gin = 0.f;
#pragma unroll
        for (int sl = 0; sl < 8; sl++) {
            gir += g_giP[sl][base + j];
            giz += g_giP[sl][base + 512 + j];
            gin += g_giP[sl][base + 1024 + j];
        }
        float ghr = 0.f, ghz = 0.f, ghn = 0.f;
#pragma unroll
        for (int sl = 0; sl < 4; sl++) {
            ghr += g_ghP[sl][base + j];
            ghz += g_ghP[sl][base + 512 + j];
            ghn += g_ghP[sl][base + 1024 + j];
        }
        float r = fast_sigmoid(gir + b_ih[j] + ghr + b_hh[j]);
        float z = fast_sigmoid(giz + b_ih[512 + j] + ghz + b_hh[512 + j]);
        float n = fast_tanh(gin + b_ih[1024 + j] + r * (ghn + b_hh[1024 + j]));
        float h = g_h[idx];
        g_h[idx] = (1.0f - z) * n + z * h;
    }
}

// ---------------- attention scores: persistent, fp16 keys ----------------
__global__ __launch_bounds__(256, 2) void scores_kernel(const float* __restrict__ v_vec) {
    const int b = blockIdx.y;
    const int tg = blockIdx.x;
    const int tid = threadIdx.x;
    const int s0 = tid * 2;

    __shared__ float s_win[TT + KW - 1];   // 46
    __shared__ float s_red[8][TT + 1];

    // persistent per-block state
    u64 qv2 = *(const u64*)(g_qbias + s0);
#pragma unroll
    for (int sl = 0; sl < 8; sl++)
        qv2 = add2(qv2, *(const u64*)(&g_qP[sl][b * S + s0]));

    u64 cw2[KW];
#pragma unroll
    for (int k = 0; k < KW; k++)
        cw2[k] = *(const u64*)(g_cwT + k * S + s0);

    float2 vv = *(const float2*)(v_vec + s0);
    const __half* kp0 = g_keysTh + ((size_t)b * S + s0) * TF;

    for (int tt = 0; tt < NTILE; tt++) {
        const int t0 = tg * (NTILE * TT) + tt * TT;

        if (tid < TT + KW - 1) {
            int t = t0 + tid - PAD;
            s_win[tid] = (t >= 0 && t < TF) ? g_w[b * TF + t] : 0.0f;
        }
        __syncthreads();

        // keys fp16 -> acc (2 x uint4 per row = 16 t's)
        uint4 a0 = *(const uint4*)(kp0 + t0);
        uint4 a1 = *(const uint4*)(kp0 + t0 + 8);
        uint4 c0 = *(const uint4*)(kp0 + TF + t0);
        uint4 c1 = *(const uint4*)(kp0 + TF + t0 + 8);
        unsigned ra[8] = {a0.x, a0.y, a0.z, a0.w, a1.x, a1.y, a1.z, a1.w};
        unsigned rc[8] = {c0.x, c0.y, c0.z, c0.w, c1.x, c1.y, c1.z, c1.w};

        u64 acc[TT];
#pragma unroll
        for (int j2 = 0; j2 < 8; j2++) {
            float l0, h0, l1, h1;
            h2f(ra[j2], l0, h0);
            h2f(rc[j2], l1, h1);
            acc[2 * j2]     = add2(pack2(l0, l1), qv2);
            acc[2 * j2 + 1] = add2(pack2(h0, h1), qv2);
        }

        // diagonal-ordered conv: one broadcast per window element, packed FMA2
#pragma unroll
        for (int i = 0; i < TT + KW - 1; i++) {
            u64 wv2 = pack2(s_win[i], s_win[i]);
#pragma unroll
            for (int j = 0; j < TT; j++) {
                int k = i - j;
                if (k >= 0 && k < KW) acc[j] = fma2(cw2[k], wv2, acc[j]);
            }
        }

        // tanh both lanes, weight by v, reduce over s
#pragma unroll
        for (int j = 0; j < TT; j++) {
            float x0, x1; unpack2(acc[j], x0, x1);
            float cv = vv.x * fast_tanh(x0) + vv.y * fast_tanh(x1);
#pragma unroll
            for (int off = 16; off > 0; off >>= 1)
                cv += __shfl_xor_sync(0xffffffffu, cv, off);
            if ((tid & 31) == 0) s_red[tid >> 5][j] = cv;
        }
        __syncthreads();
        if (tid < TT) {
            float sum = 0.0f;
#pragma unroll
            for (int w = 0; w < 8; w++) sum += s_red[w][tid];
            g_scores[b * TF + t0 + tid] = sum;
        }
    }
}

// ---------------- fused softmax + context (fp16 features, t-split partials) ----------------
// grid (2, B), 256 threads. Both blocks recompute the row softmax; block x==0
// writes g_w/ws. Each block accumulates its t-half into g_ctxP[x] for ALL 512 d
// (2 d's per thread via half2).
__global__ __launch_bounds__(256) void ctxsm_kernel(float* __restrict__ ws, int t_step)
{
    int b = blockIdx.y, x = blockIdx.x, tid = threadIdx.x;
    __shared__ float s_w[TF];
    __shared__ float s_r[8];

    float vals[4];
    float m = -1e30f;
#pragma unroll
    for (int i = 0; i < 4; i++) {
        vals[i] = g_scores[b * TF + tid + i * 256];
        m = fmaxf(m, vals[i]);
    }
#pragma unroll
    for (int off = 16; off > 0; off >>= 1)
        m = fmaxf(m, __shfl_xor_sync(0xffffffffu, m, off));
    if ((tid & 31) == 0) s_r[tid >> 5] = m;
    __syncthreads();
    m = s_r[0];
#pragma unroll
    for (int w = 1; w < 8; w++) m = fmaxf(m, s_r[w]);
    __syncthreads();

    float sum = 0.0f;
#pragma unroll
    for (int i = 0; i < 4; i++) { vals[i] = __expf(vals[i] - m); sum += vals[i]; }
#pragma unroll
    for (int off = 16; off > 0; off >>= 1)
        sum += __shfl_xor_sync(0xffffffffu, sum, off);
    if ((tid & 31) == 0) s_r[tid >> 5] = sum;
    __syncthreads();
    float total = 0.0f;
#pragma unroll
    for (int w = 0; w < 8; w++) total += s_r[w];
    float inv = __fdividef(1.0f, total);
#pragma unroll
    for (int i = 0; i < 4; i++) {
        int t = tid + i * 256;
        float wv = vals[i] * inv;
        s_w[t] = wv;
        if (x == 0) {
            g_w[b * TF + t] = wv;
            ws[((size_t)b * TD + t_step) * (size_t)TF + t] = wv;
        }
    }
    __syncthreads();

    // ctx partial: this block's t-half, all 512 d (2 per thread)
    int d0 = tid * 2;
    const __half* fb = g_featH + ((size_t)b * TF + x * 512) * S + d0;
    const float* wp = s_w + x * 512;
    float p0 = 0.f, p1 = 0.f, q0 = 0.f, q1 = 0.f, r0 = 0.f, r1 = 0.f, u0 = 0.f, u1 = 0.f;
#pragma unroll 2
    for (int t = 0; t < 512; t += 4) {
        __half2 v0 = *(const __half2*)(fb + (size_t)(t + 0) * S);
        __half2 v1 = *(const __half2*)(fb + (size_t)(t + 1) * S);
        __half2 v2 = *(const __half2*)(fb + (size_t)(t + 2) * S);
        __half2 v3 = *(const __half2*)(fb + (size_t)(t + 3) * S);
        float2 f0 = __half22float2(v0);
        float2 f1 = __half22float2(v1);
        float2 f2 = __half22float2(v2);
        float2 f3 = __half22float2(v3);
        float w0 = wp[t + 0], w1 = wp[t + 1], w2 = wp[t + 2], w3 = wp[t + 3];
        p0 = fmaf(w0, f0.x, p0); p1 = fmaf(w0, f0.y, p1);
        q0 = fmaf(w1, f1.x, q0); q1 = fmaf(w1, f1.y, q1);
        r0 = fmaf(w2, f2.x, r0); r1 = fmaf(w2, f2.y, r1);
        u0 = fmaf(w3, f3.x, u0); u1 = fmaf(w3, f3.y, u1);
    }
    g_ctxP[x][b * S + d0]     = (p0 + q0) + (r0 + u0);
    g_ctxP[x][b * S + d0 + 1] = (p1 + q1) + (r1 + u1);
}

// ---------------- launch ----------------
extern "C" void kernel_launch(void* const* d_in, const int* in_sizes, int n_in,
                              void* d_out, int out_size) {
    const int*   input    = (const int*)d_in[0];
    const float* features = (const float*)d_in[1];
    const float* emb      = (const float*)d_in[2];
    const float* W_ih     = (const float*)d_in[3];
    const float* W_hh     = (const float*)d_in[4];
    const float* b_ih     = (const float*)d_in[5];
    const float* b_hh     = (const float*)d_in[6];
    const float* Wq       = (const float*)d_in[7];
    const float* bq       = (const float*)d_in[8];
    const float* Wk       = (const float*)d_in[9];
    const float* bk       = (const float*)d_in[10];
    const float* conv_w   = (const float*)d_in[11];
    const float* conv_b   = (const float*)d_in[12];
    const float* v_vec    = (const float*)d_in[13];
    const float* Wo       = (const float*)d_in[14];
    const float* bo       = (const float*)d_in[15];

    float* outs = (float*)d_out;                        // [B, TD, V]
    float* ws   = outs + (size_t)B * TD * V;            // [B, TD, TF]

    init_kernel<<<(B * TF + 255) / 256, 256>>>();
    cw_transpose_kernel<<<(S * KW + 255) / 256, 256>>>(conv_w, bq, conv_b);
    feat_convert_kernel<<<(int)(((size_t)B * TF * S / 4) / 256), 256>>>(features);
    keys_gemm_kernel<<<dim3((B * TF) / 64, S / 64), 256>>>(features, Wk, bk);

    // prologue: gate partials for t=0 (h0 = ctx0 = 0): modes 0 (8) + 1 (4)
    gemm64_kernel<<<dim3(24, 12), 256>>>(0, input, emb, W_ih, W_hh, Wq, Wo, 0);

    for (int t = 0; t < TD; ++t) {
        // finalize logits of t-1 (if any) + combine gate partials -> h_t
        h_update_kernel<<<128, 256>>>(outs, bo, b_ih, b_hh, t - 1, 1);
        // q partials (mode 2, 8 K-slices of 64)
        gemm64_kernel<<<dim3(S / 64, 8), 256>>>(2, input, emb, W_ih, W_hh, Wq, Wo, t);
        scores_kernel<<<dim3(TF / (TT * NTILE), B), 256>>>(v_vec);
        ctxsm_kernel<<<dim3(2, B), 256>>>(ws, t);
        if (t < TD - 1) {
            // combined: gates t+1 (y 0..11) + logits partials t (y 12..19)
            gemm64_kernel<<<dim3(24, 20), 256>>>(0, input, emb, W_ih, W_hh, Wq, Wo, t + 1);
        } else {
            gemm64_kernel<<<dim3(16, 8), 256>>>(3, input, emb, W_ih, W_hh, Wq, Wo, t);
        }
    }
    // epilogue: finalize logits of final step
    h_update_kernel<<<128, 256>>>(outs, bo, b_ih, b_hh, TD - 1, 0);
}